// round 1
// baseline (speedup 1.0000x reference)
#include <cuda_runtime.h>
#include <math.h>

#define NPTS   8192
#define RROIS  128
#define G3     216
#define MGRID  (RROIS*G3)
#define NXC    252
#define NYC    252
#define NZC    11
#define NCELL  (NXC*NYC*NZC)
#define CAP    8
#define CMID   64
#define CIN    32
#define CK     35           // 3 + CIN
#define FCH    256

// ------------------------- scratch (static device globals) -------------------------
__device__ int   g_cellcnt[NCELL];
__device__ int   g_celllist[NCELL*CAP];
__device__ int   g_nactive;
__device__ int   g_actlist[MGRID];
__device__ int   g_qcnt[MGRID];
__device__ int   g_qidx[MGRID*16];
__device__ float g_newxyz[MGRID*3];
__device__ float g_pooled[MGRID*CMID];
__device__ float g_w0t[G3*CMID*FCH];     // [g][c][o]
__device__ float g_gsum[CMID*FCH];       // [c][o] = sum_g w0t
__device__ float g_pe[CMID];             // pooled value of an empty cell
__device__ float g_x[RROIS*FCH];         // shared layer-0 output
__device__ float g_wT[7*FCH*FCH];        // transposed 256x256 matrices

#define BN_INV 0.9999949932f   // 1/sqrt(1+1e-5) computed in fp32 like the reference

__device__ __forceinline__ int cellOf(int ix,int iy,int iz){ return (ix*NYC+iy)*NZC+iz; }

// ------------------------- hash build -------------------------
__global__ void k_zero(){
  int i = blockIdx.x*blockDim.x + threadIdx.x;
  if (i < NCELL) g_cellcnt[i] = 0;
  if (i == 0)    g_nactive = 0;
}

__global__ void k_insert(const float* __restrict__ xyz){
  int i = blockIdx.x*blockDim.x + threadIdx.x;
  if (i >= NPTS) return;
  float x = xyz[3*i], y = xyz[3*i+1], z = xyz[3*i+2];
  int ix = (int)floorf((x+50.f)*2.5f); ix = min(max(ix,0), NXC-1);
  int iy = (int)floorf((y+50.f)*2.5f); iy = min(max(iy,0), NYC-1);
  int iz = (int)floorf((z+ 2.f)*2.5f); iz = min(max(iz,0), NZC-1);
  int cell = cellOf(ix,iy,iz);
  int slot = atomicAdd(&g_cellcnt[cell], 1);
  if (slot < CAP) g_celllist[cell*CAP+slot] = i;
}

// ------------------------- ball query (first 16 by index) -------------------------
__global__ void k_query(const float* __restrict__ xyz, const float* __restrict__ rois){
  int m = blockIdx.x*blockDim.x + threadIdx.x;
  if (m >= MGRID) return;
  int r  = m / G3;
  int gi = m - r*G3;
  int ixg = gi/36, iyg = (gi/6)%6, izg = gi%6;
  const float* R7 = &rois[r*7];
  float sx=R7[3], sy=R7[4], sz=R7[5];
  float lx = ((float)ixg + 0.5f)/6.0f * sx - 0.5f*sx;
  float ly = ((float)iyg + 0.5f)/6.0f * sy - 0.5f*sy;
  float lz = ((float)izg + 0.5f)/6.0f * sz - 0.5f*sz;
  float cs = (float)cos((double)R7[6]);
  float sn = (float)sin((double)R7[6]);
  float px = lx*cs - ly*sn + R7[0];
  float py = lx*sn + ly*cs + R7[1];
  float pz = lz + R7[2];
  g_newxyz[3*m]=px; g_newxyz[3*m+1]=py; g_newxyz[3*m+2]=pz;

  const float RS = 0.4001f;   // slightly inflated search radius for fp safety
  int ix0 = max((int)floorf((px-RS+50.f)*2.5f), 0);
  int ix1 = min((int)floorf((px+RS+50.f)*2.5f), NXC-1);
  int iy0 = max((int)floorf((py-RS+50.f)*2.5f), 0);
  int iy1 = min((int)floorf((py+RS+50.f)*2.5f), NYC-1);
  int iz0 = max((int)floorf((pz-RS+ 2.f)*2.5f), 0);
  int iz1 = min((int)floorf((pz+RS+ 2.f)*2.5f), NZC-1);

  int lst[16]; int cnt = 0;
  for (int ix=ix0; ix<=ix1; ix++)
    for (int iy=iy0; iy<=iy1; iy++)
      for (int iz=iz0; iz<=iz1; iz++){
        int cell = cellOf(ix,iy,iz);
        int c = g_cellcnt[cell]; c = min(c, CAP);
        for (int t=0; t<c; t++){
          int j = g_celllist[cell*CAP+t];
          float dx = xyz[3*j]-px, dy = xyz[3*j+1]-py, dz = xyz[3*j+2]-pz;
          float d2 = dx*dx + dy*dy + dz*dz;
          if (d2 < 0.16f){
            if (cnt < 16){
              int p = cnt++;
              while (p>0 && lst[p-1]>j){ lst[p]=lst[p-1]; p--; }
              lst[p]=j;
            } else if (j < lst[15]){
              int p = 15;
              while (p>0 && lst[p-1]>j){ lst[p]=lst[p-1]; p--; }
              lst[p]=j;
            }
          }
        }
      }
  g_qcnt[m] = cnt;
  for (int s=0; s<cnt; s++) g_qidx[m*16+s] = lst[s];
  if (cnt > 0){ int p = atomicAdd(&g_nactive, 1); g_actlist[p] = m; }
}

// ------------------------- weight prep -------------------------
// transpose shared_w0 [256][13824] -> w0t[(g*64+c)][256]  (col = c*216+g)
__global__ void k_tw0(const float* __restrict__ w){
  __shared__ float tile[32][33];
  int col0 = blockIdx.x*32, o0 = blockIdx.y*32;
  int tx = threadIdx.x, ty = threadIdx.y;
  tile[ty][tx] = w[(o0+ty)*13824 + col0+tx];
  __syncthreads();
  int col = col0 + ty;
  int c = col / G3, g = col - c*G3;
  g_w0t[(g*CMID + c)*FCH + (o0+tx)] = tile[tx][ty];
}

__global__ void k_gsum(){
  int t = blockIdx.x*blockDim.x + threadIdx.x;   // 64*256
  int c = t >> 8, o = t & 255;
  float a = 0.f;
  for (int g=0; g<G3; g++) a += g_w0t[(g*CMID+c)*FCH + o];
  g_gsum[t] = a;
}

__global__ void k_pe(const float* __restrict__ w1, const float* __restrict__ g1,
                     const float* __restrict__ b1, const float* __restrict__ b0){
  __shared__ float h0e[CMID];
  int t = threadIdx.x;
  h0e[t] = fmaxf(b0[t], 0.f);
  __syncthreads();
  float acc = 0.f;
  for (int j=0;j<CMID;j++) acc += h0e[j]*w1[t*CMID+j];
  g_pe[t] = fmaxf(g1[t]*acc*BN_INV + b1[t], 0.f);
}

// transpose seven 256x256 matrices into g_wT[mat][k][o] = W[mat][o][k]
__global__ void k_t7(const float* m0,const float* m1,const float* m2,const float* m3,
                     const float* m4,const float* m5,const float* m6){
  const float* W;
  switch (blockIdx.z){
    case 0: W=m0; break; case 1: W=m1; break; case 2: W=m2; break;
    case 3: W=m3; break; case 4: W=m4; break; case 5: W=m5; break;
    default: W=m6; break;
  }
  __shared__ float tile[32][33];
  int x0 = blockIdx.x*32, y0 = blockIdx.y*32;
  int tx = threadIdx.x, ty = threadIdx.y;
  tile[ty][tx] = W[(y0+ty)*FCH + x0+tx];
  __syncthreads();
  g_wT[blockIdx.z*FCH*FCH + (x0+ty)*FCH + (y0+tx)] = tile[tx][ty];
}

// ------------------------- point MLP + max pool (nonempty cells only) -------------------------
__global__ void k_mlp(const float* __restrict__ xyz, const float* __restrict__ feat,
                      const float* __restrict__ w0, const float* __restrict__ gg0, const float* __restrict__ bb0,
                      const float* __restrict__ w1, const float* __restrict__ gg1, const float* __restrict__ bb1){
  int nact = g_nactive;
  if ((int)blockIdx.x >= nact) return;
  int t = threadIdx.x;   // 64 threads = 64 mid channels
  __shared__ float sw0[CMID*CK];
  __shared__ float sw1[CMID*65];           // padded stride 65 (avoid 32-way conflicts)
  __shared__ float sg0[CMID], sb0[CMID], sg1[CMID], sb1[CMID];
  __shared__ float grp[16*CK];
  __shared__ float h0s[16*CMID];
  for (int e=t; e<CMID*CK; e+=64) sw0[e] = w0[e];
  for (int e=t; e<CMID*CMID; e+=64){ int c=e>>6, j=e&63; sw1[c*65+j]=w1[e]; }
  sg0[t]=gg0[t]; sb0[t]=bb0[t]; sg1[t]=gg1[t]; sb1[t]=bb1[t];

  for (int it = blockIdx.x; it < nact; it += gridDim.x){
    int m   = g_actlist[it];
    int cnt = g_qcnt[m];
    float nx=g_newxyz[3*m], ny=g_newxyz[3*m+1], nz=g_newxyz[3*m+2];
    __syncthreads();
    for (int e=t; e<cnt*CK; e+=64){
      int s = e/CK, k = e - s*CK;
      int j = g_qidx[m*16+s];
      float v;
      if (k < 3) v = xyz[3*j+k] - ((k==0)?nx:((k==1)?ny:nz));
      else       v = feat[j*CIN + (k-3)];
      grp[e] = v;
    }
    __syncthreads();
    for (int s=0; s<cnt; s++){
      float acc = 0.f;
      #pragma unroll
      for (int k=0;k<CK;k++) acc += grp[s*CK+k]*sw0[t*CK+k];
      h0s[s*CMID+t] = fmaxf(sg0[t]*acc*BN_INV + sb0[t], 0.f);
    }
    __syncthreads();
    float best = 0.f;   // relu outputs are >= 0 and cnt>=1
    for (int s=0; s<cnt; s++){
      float acc = 0.f;
      #pragma unroll 16
      for (int j=0;j<CMID;j++) acc += h0s[s*CMID+j]*sw1[t*65+j];
      best = fmaxf(best, fmaxf(sg1[t]*acc*BN_INV + sb1[t], 0.f));
    }
    g_pooled[m*CMID+t] = best;
  }
}

// ------------------------- sparse shared_w0 layer -------------------------
__global__ void k_sh0(){
  int r = blockIdx.x, o = threadIdx.x;   // 128 blocks x 256 threads
  __shared__ float spe[CMID];
  __shared__ float sdelta[CMID];
  __shared__ int   scnt[G3];
  if (o < CMID) spe[o] = g_pe[o];
  if (o < G3)   scnt[o] = g_qcnt[r*G3+o];
  __syncthreads();
  float acc = 0.f;
  #pragma unroll 8
  for (int c=0;c<CMID;c++) acc += spe[c]*g_gsum[c*FCH+o];
  for (int g=0; g<G3; g++){
    if (scnt[g] > 0){
      __syncthreads();
      if (o < CMID) sdelta[o] = g_pooled[(r*G3+g)*CMID+o] - spe[o];
      __syncthreads();
      const float* wp = &g_w0t[(g*CMID)*FCH + o];
      #pragma unroll 8
      for (int c=0;c<CMID;c++) acc += sdelta[c]*wp[c*FCH];
    }
  }
  g_x[r*FCH+o] = fmaxf(acc, 0.f);
}

// ------------------------- fused head MLPs -------------------------
__device__ __forceinline__ void layerE(float* dst, const float* src,
                                       const float* __restrict__ WT, int t){
  float a0=0.f, a1=0.f;
  const float2* s2 = (const float2*)src;
  #pragma unroll 8
  for (int k=0;k<FCH;k++){
    float w = WT[k*FCH + t];
    float2 sv = s2[k];
    a0 += sv.x*w; a1 += sv.y*w;
  }
  dst[2*t]   = fmaxf(a0, 0.f);
  dst[2*t+1] = fmaxf(a1, 0.f);
  __syncthreads();
}

__device__ __forceinline__ void headOut(const float* S, const float* __restrict__ w2,
                                        const float* __restrict__ b2,
                                        float* out, int rb, int nq, int t){
  int w = t>>5, lane = t&31;
  if (w < 2){
    for (int q=0;q<nq;q++){
      float s = 0.f;
      for (int k=lane;k<FCH;k+=32) s += S[2*k+w]*w2[q*FCH+k];
      #pragma unroll
      for (int off=16;off;off>>=1) s += __shfl_down_sync(0xffffffffu, s, off);
      if (lane==0) out[(rb+w)*nq+q] = s + b2[q];
    }
  }
  __syncthreads();
}

__global__ void k_heads(const float* __restrict__ cw2,const float* __restrict__ cb2,
                        const float* __restrict__ iw2,const float* __restrict__ ib2,
                        const float* __restrict__ rw2,const float* __restrict__ rb2,
                        float* __restrict__ out){
  __shared__ float S0[2*FCH], S1[2*FCH], S2[2*FCH];
  int t = threadIdx.x;
  int rb = blockIdx.x*2;                   // 2 rois per block
  for (int e=t; e<2*FCH; e+=FCH){ int k=e>>1, rr=e&1; S0[e] = g_x[(rb+rr)*FCH + k]; }
  __syncthreads();
  layerE(S1, S0, &g_wT[0*FCH*FCH], t);     // shared_w1
  // cls
  layerE(S2, S1, &g_wT[1*FCH*FCH], t);
  layerE(S0, S2, &g_wT[2*FCH*FCH], t);
  headOut(S0, cw2, cb2, out + 0, rb, 1, t);
  // iou
  layerE(S2, S1, &g_wT[3*FCH*FCH], t);
  layerE(S0, S2, &g_wT[4*FCH*FCH], t);
  headOut(S0, iw2, ib2, out + RROIS, rb, 1, t);
  // reg
  layerE(S2, S1, &g_wT[5*FCH*FCH], t);
  layerE(S0, S2, &g_wT[6*FCH*FCH], t);
  headOut(S0, rw2, rb2, out + 2*RROIS, rb, 7, t);
}

// ------------------------- launch -------------------------
extern "C" void kernel_launch(void* const* d_in, const int* in_sizes, int n_in,
                              void* d_out, int out_size){
  const float* xyz    = (const float*)d_in[0];
  const float* feat   = (const float*)d_in[1];
  const float* rois   = (const float*)d_in[2];
  const float* mlp_w0 = (const float*)d_in[3];
  const float* mlp_g0 = (const float*)d_in[4];
  const float* mlp_b0 = (const float*)d_in[5];
  const float* mlp_w1 = (const float*)d_in[6];
  const float* mlp_g1 = (const float*)d_in[7];
  const float* mlp_b1 = (const float*)d_in[8];
  const float* sw0    = (const float*)d_in[9];
  const float* sw1    = (const float*)d_in[10];
  const float* cw0    = (const float*)d_in[11];
  const float* cw1    = (const float*)d_in[12];
  const float* cw2    = (const float*)d_in[13];
  const float* cb2    = (const float*)d_in[14];
  const float* iw0    = (const float*)d_in[15];
  const float* iw1    = (const float*)d_in[16];
  const float* iw2    = (const float*)d_in[17];
  const float* ib2    = (const float*)d_in[18];
  const float* rw0    = (const float*)d_in[19];
  const float* rw1    = (const float*)d_in[20];
  const float* rw2    = (const float*)d_in[21];
  const float* rb2    = (const float*)d_in[22];
  float* out = (float*)d_out;

  k_zero  <<<(NCELL+255)/256, 256>>>();
  k_insert<<<NPTS/256, 256>>>(xyz);
  k_query <<<MGRID/256, 256>>>(xyz, rois);
  k_tw0   <<<dim3(13824/32, FCH/32), dim3(32,32)>>>(sw0);
  k_gsum  <<<(CMID*FCH)/256, 256>>>();
  k_pe    <<<1, 64>>>(mlp_w1, mlp_g1, mlp_b1, mlp_b0);
  k_t7    <<<dim3(8,8,7), dim3(32,32)>>>(sw1, cw0, cw1, iw0, iw1, rw0, rw1);
  k_mlp   <<<1792, 64>>>(xyz, feat, mlp_w0, mlp_g0, mlp_b0, mlp_w1, mlp_g1, mlp_b1);
  k_sh0   <<<RROIS, 256>>>();
  k_heads <<<RROIS/2, 256>>>(cw2, cb2, iw2, ib2, rw2, rb2, out);
}

// round 3
// speedup vs baseline: 2.0895x; 2.0895x over previous
#include <cuda_runtime.h>
#include <math.h>

#define NPTS   8192
#define RROIS  128
#define G3     216
#define MGRID  (RROIS*G3)
#define NXC    252
#define NYC    252
#define NZC    11
#define NCELL  (NXC*NYC*NZC)      // 698544
#define CAP    8
#define CMID   64
#define CIN    32
#define CK     35
#define FCH    256

// ------------------------- scratch -------------------------
__device__ int   g_cellcnt[NCELL];
__device__ int   g_celllist[NCELL*CAP];
__device__ int   g_nactive;
__device__ int   g_actlist[MGRID];
__device__ int   g_qcnt[MGRID];
__device__ int   g_qidx[MGRID*16];
__device__ float g_newxyz[MGRID*3];
__device__ float g_pooled[MGRID*CMID];
__device__ float g_w0t[G3*CMID*FCH];       // [g*64+c][o], o contiguous
__device__ float g_base[FCH];              // baseline output of sparse layer
__device__ float g_pe[CMID];               // empty-cell pooled vector
__device__ float g_x[RROIS*FCH];
__device__ float g_wT[7*FCH*FCH];          // packed: [mat][k4][o][ki]

#define BN_INV 0.9999949932f

__device__ __forceinline__ int cellOf(int ix,int iy,int iz){ return (ix*NYC+iy)*NZC+iz; }

// ------------------------- fused prep kernel -------------------------
// blocks [0,864)    : transpose sw0 [256][13824] -> g_w0t[(g*64+c)][o]   (64x64 tiles, float4)
// blocks [864,976)  : pack 7 256x256 mats -> g_wT[mat][k4][o][ki]         (64x64 tiles)
// blocks [976,1232) : g_base[o] = sum_col sw0[o][col]*pe[col/216], also writes g_pe
// blocks [1232,1403): zero g_cellcnt, g_nactive
__global__ void k_prep(const float* __restrict__ sw0,
                       const float* __restrict__ m0,const float* __restrict__ m1,
                       const float* __restrict__ m2,const float* __restrict__ m3,
                       const float* __restrict__ m4,const float* __restrict__ m5,
                       const float* __restrict__ m6,
                       const float* __restrict__ w1,const float* __restrict__ g1v,
                       const float* __restrict__ b1v,const float* __restrict__ b0v){
  __shared__ float sh[64*65];    // 16.6KB, reused per role
  int b = blockIdx.x, tid = threadIdx.x;
  int tx = tid & 15, ty = tid >> 4;

  if (b < 864){
    int ct = b % 216, ot = b / 216;
    int col0 = ct*64, o0 = ot*64;
    #pragma unroll
    for (int i=0;i<4;i++){
      int r = ty + 16*i;
      float4 v = *(const float4*)&sw0[(size_t)(o0+r)*13824 + col0 + 4*tx];
      float* t = &sh[r*65 + 4*tx];
      t[0]=v.x; t[1]=v.y; t[2]=v.z; t[3]=v.w;
    }
    __syncthreads();
    #pragma unroll
    for (int i=0;i<4;i++){
      int ci = ty + 16*i;
      int col = col0 + ci;
      int c = col / 216, g = col - c*216;
      float4 v;
      v.x = sh[(4*tx+0)*65 + ci];
      v.y = sh[(4*tx+1)*65 + ci];
      v.z = sh[(4*tx+2)*65 + ci];
      v.w = sh[(4*tx+3)*65 + ci];
      *(float4*)&g_w0t[(g*CMID + c)*FCH + o0 + 4*tx] = v;
    }
  } else if (b < 976){
    int bb = b - 864;
    int mat = bb >> 4, tt = bb & 15;
    int kt = tt & 3, ot = tt >> 2;
    const float* W = (mat==0)?m0:(mat==1)?m1:(mat==2)?m2:(mat==3)?m3:(mat==4)?m4:(mat==5)?m5:m6;
    int k0 = kt*64, o0 = ot*64;
    #pragma unroll
    for (int i=0;i<4;i++){
      int r = ty + 16*i;     // o index within tile
      float4 v = *(const float4*)&W[(o0+r)*FCH + k0 + 4*tx];
      float* t = &sh[r*65 + 4*tx];
      t[0]=v.x; t[1]=v.y; t[2]=v.z; t[3]=v.w;
    }
    __syncthreads();
    #pragma unroll
    for (int i=0;i<4;i++){
      int idx = tid + 256*i;         // 1024 float4 outputs
      int ol = idx & 63, k4l = idx >> 6;
      float4 v;
      v.x = sh[ol*65 + 4*k4l+0];
      v.y = sh[ol*65 + 4*k4l+1];
      v.z = sh[ol*65 + 4*k4l+2];
      v.w = sh[ol*65 + 4*k4l+3];
      int k4g = (k0>>2) + k4l;
      *(float4*)&g_wT[mat*FCH*FCH + k4g*1024 + (o0+ol)*4] = v;
    }
  } else if (b < 1232){
    int o = b - 976;
    float* spe = sh;           // [0,64)
    float* h0e = sh + 64;      // [64,128)
    float* red = sh + 128;     // [128,384)
    if (tid < 64) h0e[tid] = fmaxf(b0v[tid], 0.f);
    __syncthreads();
    if (tid < 64){
      float acc = 0.f;
      #pragma unroll 8
      for (int j=0;j<CMID;j++) acc += h0e[j]*w1[tid*CMID+j];
      spe[tid] = fmaxf(g1v[tid]*acc*BN_INV + b1v[tid], 0.f);
    }
    __syncthreads();
    float s = 0.f;
    const float4* row4 = (const float4*)&sw0[(size_t)o*13824];
    for (int it=tid; it<3456; it+=256){
      float4 v = row4[it];
      int col = it*4;
      int c0 = col/216; int rem = col - c0*216;
      float p0 = spe[c0];
      float p1 = spe[(rem+1>=216)? c0+1 : c0];
      float p2 = spe[(rem+2>=216)? c0+1 : c0];
      float p3 = spe[(rem+3>=216)? c0+1 : c0];
      s += v.x*p0 + v.y*p1 + v.z*p2 + v.w*p3;
    }
    red[tid] = s; __syncthreads();
    if (tid<128) red[tid] += red[tid+128]; __syncthreads();
    if (tid<64)  red[tid] += red[tid+64];  __syncthreads();
    if (tid<32){
      float v = red[tid] + red[tid+32];
      #pragma unroll
      for (int off=16;off;off>>=1) v += __shfl_down_sync(0xffffffffu, v, off);
      if (tid==0) g_base[o] = v;
    }
    if (b==976 && tid<64) g_pe[tid] = spe[tid];
  } else {
    int d = b - 1232;
    int4 z = make_int4(0,0,0,0);
    for (int i = d*256 + tid; i < NCELL/4; i += 171*256)
      ((int4*)g_cellcnt)[i] = z;
    if (d==0 && tid==0) g_nactive = 0;
  }
}

// ------------------------- hash insert -------------------------
__global__ void k_insert(const float* __restrict__ xyz){
  int i = blockIdx.x*blockDim.x + threadIdx.x;
  if (i >= NPTS) return;
  float x = xyz[3*i], y = xyz[3*i+1], z = xyz[3*i+2];
  int ix = (int)floorf((x+50.f)*2.5f); ix = min(max(ix,0), NXC-1);
  int iy = (int)floorf((y+50.f)*2.5f); iy = min(max(iy,0), NYC-1);
  int iz = (int)floorf((z+ 2.f)*2.5f); iz = min(max(iz,0), NZC-1);
  int cell = cellOf(ix,iy,iz);
  int slot = atomicAdd(&g_cellcnt[cell], 1);
  if (slot < CAP) g_celllist[cell*CAP+slot] = i;
}

// ------------------------- ball query (first 16 by index) -------------------------
__global__ void k_query(const float* __restrict__ xyz, const float* __restrict__ rois){
  int m = blockIdx.x*blockDim.x + threadIdx.x;
  if (m >= MGRID) return;
  int r  = m / G3;
  int gi = m - r*G3;
  int ixg = gi/36, iyg = (gi/6)%6, izg = gi%6;
  const float* R7 = &rois[r*7];
  float sx=R7[3], sy=R7[4], sz=R7[5];
  float lx = ((float)ixg + 0.5f)/6.0f * sx - 0.5f*sx;
  float ly = ((float)iyg + 0.5f)/6.0f * sy - 0.5f*sy;
  float lz = ((float)izg + 0.5f)/6.0f * sz - 0.5f*sz;
  float cs = (float)cos((double)R7[6]);
  float sn = (float)sin((double)R7[6]);
  float px = lx*cs - ly*sn + R7[0];
  float py = lx*sn + ly*cs + R7[1];
  float pz = lz + R7[2];
  g_newxyz[3*m]=px; g_newxyz[3*m+1]=py; g_newxyz[3*m+2]=pz;

  const float RS = 0.4001f;
  int ix0 = max((int)floorf((px-RS+50.f)*2.5f), 0);
  int ix1 = min((int)floorf((px+RS+50.f)*2.5f), NXC-1);
  int iy0 = max((int)floorf((py-RS+50.f)*2.5f), 0);
  int iy1 = min((int)floorf((py+RS+50.f)*2.5f), NYC-1);
  int iz0 = max((int)floorf((pz-RS+ 2.f)*2.5f), 0);
  int iz1 = min((int)floorf((pz+RS+ 2.f)*2.5f), NZC-1);

  int lst[16]; int cnt = 0;
  for (int ix=ix0; ix<=ix1; ix++)
    for (int iy=iy0; iy<=iy1; iy++)
      for (int iz=iz0; iz<=iz1; iz++){
        int cell = cellOf(ix,iy,iz);
        int c = g_cellcnt[cell]; c = min(c, CAP);
        for (int t=0; t<c; t++){
          int j = g_celllist[cell*CAP+t];
          float dx = xyz[3*j]-px, dy = xyz[3*j+1]-py, dz = xyz[3*j+2]-pz;
          float d2 = dx*dx + dy*dy + dz*dz;
          if (d2 < 0.16f){
            if (cnt < 16){
              int p = cnt++;
              while (p>0 && lst[p-1]>j){ lst[p]=lst[p-1]; p--; }
              lst[p]=j;
            } else if (j < lst[15]){
              int p = 15;
              while (p>0 && lst[p-1]>j){ lst[p]=lst[p-1]; p--; }
              lst[p]=j;
            }
          }
        }
      }
  g_qcnt[m] = cnt;
  for (int s=0; s<cnt; s++) g_qidx[m*16+s] = lst[s];
  if (cnt > 0){ int p = atomicAdd(&g_nactive, 1); g_actlist[p] = m; }
}

// ------------------------- point MLP + max pool -------------------------
__global__ void k_mlp(const float* __restrict__ xyz, const float* __restrict__ feat,
                      const float* __restrict__ w0, const float* __restrict__ gg0, const float* __restrict__ bb0,
                      const float* __restrict__ w1, const float* __restrict__ gg1, const float* __restrict__ bb1){
  int nact = g_nactive;
  if ((int)blockIdx.x >= nact) return;
  int t = threadIdx.x;   // 64 threads = channels
  __shared__ __align__(16) float sw0s[CMID*CK];   // 2240
  __shared__ float sw1s[CMID*65];
  __shared__ float sg0[CMID], sb0[CMID], sg1[CMID], sb1[CMID];
  __shared__ float grp[16*CK];
  __shared__ float h0s[16*CMID];
  const float4* w04 = (const float4*)w0;
  for (int e=t; e<560; e+=64) ((float4*)sw0s)[e] = w04[e];
  const float4* w14 = (const float4*)w1;
  for (int e=t; e<1024; e+=64){
    float4 v = w14[e];
    int c = e>>4, j0 = (e&15)*4;
    float* p = &sw1s[c*65 + j0];
    p[0]=v.x; p[1]=v.y; p[2]=v.z; p[3]=v.w;
  }
  sg0[t]=gg0[t]; sb0[t]=bb0[t]; sg1[t]=gg1[t]; sb1[t]=bb1[t];

  for (int it = blockIdx.x; it < nact; it += gridDim.x){
    int m   = g_actlist[it];
    int cnt = g_qcnt[m];
    float nx=g_newxyz[3*m], ny=g_newxyz[3*m+1], nz=g_newxyz[3*m+2];
    __syncthreads();
    for (int e=t; e<cnt*CK; e+=64){
      int s = e/CK, k = e - s*CK;
      int j = g_qidx[m*16+s];
      float v;
      if (k < 3) v = xyz[3*j+k] - ((k==0)?nx:((k==1)?ny:nz));
      else       v = feat[j*CIN + (k-3)];
      grp[e] = v;
    }
    __syncthreads();
    for (int s=0; s<cnt; s++){
      float acc = 0.f;
      #pragma unroll
      for (int k=0;k<CK;k++) acc += grp[s*CK+k]*sw0s[t*CK+k];
      h0s[s*CMID+t] = fmaxf(sg0[t]*acc*BN_INV + sb0[t], 0.f);
    }
    __syncthreads();
    float best = 0.f;
    for (int s=0; s<cnt; s++){
      float acc = 0.f;
      #pragma unroll 16
      for (int j=0;j<CMID;j++) acc += h0s[s*CMID+j]*sw1s[t*65+j];
      best = fmaxf(best, fmaxf(sg1[t]*acc*BN_INV + sb1[t], 0.f));
    }
    g_pooled[m*CMID+t] = best;
  }
}

// ------------------------- sparse shared_w0 layer -------------------------
__global__ void k_sh0(){
  int r = blockIdx.x, o = threadIdx.x;   // 128 blocks x 256 threads
  __shared__ float spe[CMID], d0[CMID], d1[CMID];
  __shared__ int list[G3], wcnt[8], nn;
  if (o < CMID) spe[o] = g_pe[o];
  int flag = (o < G3) ? (g_qcnt[r*G3+o] > 0) : 0;
  unsigned bal = __ballot_sync(0xffffffffu, flag);
  if ((o&31)==0) wcnt[o>>5] = __popc(bal);
  __syncthreads();
  if (o==0){ int s=0; for (int w=0;w<8;w++){ int c=wcnt[w]; wcnt[w]=s; s+=c; } nn=s; }
  __syncthreads();
  if (flag){
    int pos = wcnt[o>>5] + __popc(bal & ((1u<<(o&31))-1u));
    list[pos] = o;
  }
  __syncthreads();
  float acc = g_base[o];
  int n = nn;
  for (int i=0; i<n; i+=2){
    int ga = list[i];
    int gb = (i+1<n)? list[i+1] : -1;
    if (o < CMID)                   d0[o]    = g_pooled[(r*G3+ga)*CMID+o]    - spe[o];
    else if (o < 2*CMID && gb>=0)   d1[o-64] = g_pooled[(r*G3+gb)*CMID+o-64] - spe[o-64];
    __syncthreads();
    const float* wa = &g_w0t[(ga*CMID)*FCH + o];
    float acc2 = 0.f;
    #pragma unroll 16
    for (int c=0;c<CMID;c++) acc += d0[c]*wa[c*FCH];
    if (gb>=0){
      const float* wb = &g_w0t[(gb*CMID)*FCH + o];
      #pragma unroll 16
      for (int c=0;c<CMID;c++) acc2 += d1[c]*wb[c*FCH];
      acc += acc2;
    }
    __syncthreads();
  }
  g_x[r*FCH+o] = fmaxf(acc, 0.f);
}

// ------------------------- fused head MLPs -------------------------
__device__ __forceinline__ void layerP(int mat, const float* s0, const float* s1,
                                       float* dst0, float* dst1, int t){
  const float4* P  = (const float4*)&g_wT[mat*FCH*FCH];
  const float4* v0 = (const float4*)s0;
  const float4* v1 = (const float4*)s1;
  float a0=0.f, a1=0.f;
  #pragma unroll 8
  for (int k4=0;k4<64;k4++){
    float4 w = P[k4*FCH + t];
    float4 x0 = v0[k4], x1 = v1[k4];
    a0 += w.x*x0.x; a0 += w.y*x0.y; a0 += w.z*x0.z; a0 += w.w*x0.w;
    a1 += w.x*x1.x; a1 += w.y*x1.y; a1 += w.z*x1.z; a1 += w.w*x1.w;
  }
  dst0[t]=fmaxf(a0,0.f); dst1[t]=fmaxf(a1,0.f);
  __syncthreads();
}

__global__ void k_heads(const float* __restrict__ cw2,const float* __restrict__ cb2,
                        const float* __restrict__ iw2,const float* __restrict__ ib2,
                        const float* __restrict__ rw2,const float* __restrict__ rb2,
                        float* __restrict__ out){
  __shared__ __align__(16) float SA0[FCH], SA1[FCH], SB0[FCH], SB1[FCH];
  int t = threadIdx.x;
  int rb = blockIdx.x*2, h = blockIdx.y;
  SA0[t] = g_x[rb*FCH+t]; SA1[t] = g_x[(rb+1)*FCH+t];
  __syncthreads();
  layerP(0,       SA0,SA1, SB0,SB1, t);   // shared_w1
  layerP(1+2*h,   SB0,SB1, SA0,SA1, t);   // head layer 0
  layerP(2+2*h,   SA0,SA1, SB0,SB1, t);   // head layer 1
  const float* w2 = (h==0)? cw2 : (h==1)? iw2 : rw2;
  const float* b2 = (h==0)? cb2 : (h==1)? ib2 : rb2;
  int nq  = (h==2)? 7 : 1;
  int off = (h==0)? 0 : (h==1)? RROIS : 2*RROIS;
  int w = t>>5, lane = t&31;
  if (w < 2){
    const float* S = w ? SB1 : SB0;
    for (int q=0;q<nq;q++){
      float s = 0.f;
      for (int k=lane;k<FCH;k+=32) s += S[k]*w2[q*FCH+k];
      #pragma unroll
      for (int o2=16;o2;o2>>=1) s += __shfl_down_sync(0xffffffffu, s, o2);
      if (lane==0) out[off + (rb+w)*nq + q] = s + b2[q];
    }
  }
}

// ------------------------- launch -------------------------
extern "C" void kernel_launch(void* const* d_in, const int* in_sizes, int n_in,
                              void* d_out, int out_size){
  const float* xyz    = (const float*)d_in[0];
  const float* feat   = (const float*)d_in[1];
  const float* rois   = (const float*)d_in[2];
  const float* mlp_w0 = (const float*)d_in[3];
  const float* mlp_g0 = (const float*)d_in[4];
  const float* mlp_b0 = (const float*)d_in[5];
  const float* mlp_w1 = (const float*)d_in[6];
  const float* mlp_g1 = (const float*)d_in[7];
  const float* mlp_b1 = (const float*)d_in[8];
  const float* sw0    = (const float*)d_in[9];
  const float* sw1    = (const float*)d_in[10];
  const float* cw0    = (const float*)d_in[11];
  const float* cw1    = (const float*)d_in[12];
  const float* cw2    = (const float*)d_in[13];
  const float* cb2    = (const float*)d_in[14];
  const float* iw0    = (const float*)d_in[15];
  const float* iw1    = (const float*)d_in[16];
  const float* iw2    = (const float*)d_in[17];
  const float* ib2    = (const float*)d_in[18];
  const float* rw0    = (const float*)d_in[19];
  const float* rw1    = (const float*)d_in[20];
  const float* rw2    = (const float*)d_in[21];
  const float* rb2    = (const float*)d_in[22];
  float* out = (float*)d_out;

  k_prep  <<<1403, 256>>>(sw0, sw1, cw0, cw1, iw0, iw1, rw0, rw1,
                          mlp_w1, mlp_g1, mlp_b1, mlp_b0);
  k_insert<<<NPTS/256, 256>>>(xyz);
  k_query <<<MGRID/256, 256>>>(xyz, rois);
  k_mlp   <<<592, 64>>>(xyz, feat, mlp_w0, mlp_g0, mlp_b0, mlp_w1, mlp_g1, mlp_b1);
  k_sh0   <<<RROIS, 256>>>();
  k_heads <<<dim3(RROIS/2, 3), 256>>>(cw2, cb2, iw2, ib2, rw2, rb2, out);
}

// round 4
// speedup vs baseline: 2.5632x; 1.2267x over previous
#include <cuda_runtime.h>
#include <math.h>

#define NPTS   8192
#define RROIS  128
#define G3     216
#define MGRID  (RROIS*G3)
#define NXC    252
#define NYC    252
#define NZC    11
#define NCELL  (NXC*NYC*NZC)      // 698544
#define CAP    8
#define CMID   64
#define CIN    32
#define CK     35
#define FCH    256

// ------------------------- scratch -------------------------
__device__ int   g_cellcnt[NCELL];
__device__ int   g_celllist[NCELL*CAP];
__device__ int   g_qcnt[MGRID];
__device__ int   g_qidx[MGRID*16];
__device__ float g_newxyz[MGRID*3];
__device__ float g_trig[2*RROIS];
__device__ float g_w0t[G3*CMID*FCH];       // [g*64+c][o], o contiguous
__device__ float g_base[FCH];              // baseline output of sparse layer
__device__ float g_pe[CMID];               // empty-cell pooled vector
__device__ float g_x[RROIS*FCH];
__device__ float g_wT[7*FCH*FCH];          // packed: [mat][k4][o][ki]

#define BN_INV 0.9999949932f

__device__ __forceinline__ int cellOf(int ix,int iy,int iz){ return (ix*NYC+iy)*NZC+iz; }
__device__ __forceinline__ void barg(int id){ asm volatile("bar.sync %0, 64;" :: "r"(id)); }

// ------------------------- fused prep kernel -------------------------
__global__ void k_prep(const float* __restrict__ sw0,
                       const float* __restrict__ m0,const float* __restrict__ m1,
                       const float* __restrict__ m2,const float* __restrict__ m3,
                       const float* __restrict__ m4,const float* __restrict__ m5,
                       const float* __restrict__ m6,
                       const float* __restrict__ w1,const float* __restrict__ g1v,
                       const float* __restrict__ b1v,const float* __restrict__ b0v){
  __shared__ float sh[64*65];
  int b = blockIdx.x, tid = threadIdx.x;
  int tx = tid & 15, ty = tid >> 4;

  if (b < 864){
    int ct = b % 216, ot = b / 216;
    int col0 = ct*64, o0 = ot*64;
    #pragma unroll
    for (int i=0;i<4;i++){
      int r = ty + 16*i;
      float4 v = *(const float4*)&sw0[(size_t)(o0+r)*13824 + col0 + 4*tx];
      float* t = &sh[r*65 + 4*tx];
      t[0]=v.x; t[1]=v.y; t[2]=v.z; t[3]=v.w;
    }
    __syncthreads();
    #pragma unroll
    for (int i=0;i<4;i++){
      int ci = ty + 16*i;
      int col = col0 + ci;
      int c = col / 216, g = col - c*216;
      float4 v;
      v.x = sh[(4*tx+0)*65 + ci];
      v.y = sh[(4*tx+1)*65 + ci];
      v.z = sh[(4*tx+2)*65 + ci];
      v.w = sh[(4*tx+3)*65 + ci];
      *(float4*)&g_w0t[(g*CMID + c)*FCH + o0 + 4*tx] = v;
    }
  } else if (b < 976){
    int bb = b - 864;
    int mat = bb >> 4, tt = bb & 15;
    int kt = tt & 3, ot = tt >> 2;
    const float* W = (mat==0)?m0:(mat==1)?m1:(mat==2)?m2:(mat==3)?m3:(mat==4)?m4:(mat==5)?m5:m6;
    int k0 = kt*64, o0 = ot*64;
    #pragma unroll
    for (int i=0;i<4;i++){
      int r = ty + 16*i;
      float4 v = *(const float4*)&W[(o0+r)*FCH + k0 + 4*tx];
      float* t = &sh[r*65 + 4*tx];
      t[0]=v.x; t[1]=v.y; t[2]=v.z; t[3]=v.w;
    }
    __syncthreads();
    #pragma unroll
    for (int i=0;i<4;i++){
      int idx = tid + 256*i;
      int ol = idx & 63, k4l = idx >> 6;
      float4 v;
      v.x = sh[ol*65 + 4*k4l+0];
      v.y = sh[ol*65 + 4*k4l+1];
      v.z = sh[ol*65 + 4*k4l+2];
      v.w = sh[ol*65 + 4*k4l+3];
      int k4g = (k0>>2) + k4l;
      *(float4*)&g_wT[mat*FCH*FCH + k4g*1024 + (o0+ol)*4] = v;
    }
  } else if (b < 1232){
    int o = b - 976;
    float* spe = sh;
    float* h0e = sh + 64;
    float* red = sh + 128;
    if (tid < 64) h0e[tid] = fmaxf(b0v[tid], 0.f);
    __syncthreads();
    if (tid < 64){
      float acc = 0.f;
      #pragma unroll 8
      for (int j=0;j<CMID;j++) acc += h0e[j]*w1[tid*CMID+j];
      spe[tid] = fmaxf(g1v[tid]*acc*BN_INV + b1v[tid], 0.f);
    }
    __syncthreads();
    float s = 0.f;
    const float4* row4 = (const float4*)&sw0[(size_t)o*13824];
    for (int it=tid; it<3456; it+=256){
      float4 v = row4[it];
      int col = it*4;
      int c0 = col/216; int rem = col - c0*216;
      float p0 = spe[c0];
      float p1 = spe[(rem+1>=216)? c0+1 : c0];
      float p2 = spe[(rem+2>=216)? c0+1 : c0];
      float p3 = spe[(rem+3>=216)? c0+1 : c0];
      s += v.x*p0 + v.y*p1 + v.z*p2 + v.w*p3;
    }
    red[tid] = s; __syncthreads();
    if (tid<128) red[tid] += red[tid+128]; __syncthreads();
    if (tid<64)  red[tid] += red[tid+64];  __syncthreads();
    if (tid<32){
      float v = red[tid] + red[tid+32];
      #pragma unroll
      for (int off=16;off;off>>=1) v += __shfl_down_sync(0xffffffffu, v, off);
      if (tid==0) g_base[o] = v;
    }
    if (b==976 && tid<64) g_pe[tid] = spe[tid];
  } else {
    int d = b - 1232;
    int4 z = make_int4(0,0,0,0);
    for (int i = d*256 + tid; i < NCELL/4; i += 171*256)
      ((int4*)g_cellcnt)[i] = z;
  }
}

// ------------------------- hash insert + per-roi trig -------------------------
__global__ void k_insert(const float* __restrict__ xyz, const float* __restrict__ rois){
  if (blockIdx.x == 32){
    int r = threadIdx.x;
    if (r < RROIS){
      double a = (double)rois[r*7+6];
      g_trig[2*r]   = (float)cos(a);
      g_trig[2*r+1] = (float)sin(a);
    }
    return;
  }
  int i = blockIdx.x*blockDim.x + threadIdx.x;
  float x = xyz[3*i], y = xyz[3*i+1], z = xyz[3*i+2];
  int ix = (int)floorf((x+50.f)*2.5f); ix = min(max(ix,0), NXC-1);
  int iy = (int)floorf((y+50.f)*2.5f); iy = min(max(iy,0), NYC-1);
  int iz = (int)floorf((z+ 2.f)*2.5f); iz = min(max(iz,0), NZC-1);
  int cell = cellOf(ix,iy,iz);
  int slot = atomicAdd(&g_cellcnt[cell], 1);
  if (slot < CAP) g_celllist[cell*CAP+slot] = i;
}

// ------------------------- ball query, block per roi -------------------------
__global__ void k_query(const float* __restrict__ xyz, const float* __restrict__ rois){
  int r = blockIdx.x, tid = threadIdx.x;
  __shared__ float R7[7], trg[2];
  if (tid < 7) R7[tid] = rois[r*7+tid];
  if (tid < 2) trg[tid] = g_trig[2*r+tid];
  __syncthreads();
  if (tid >= G3) return;
  int m = r*G3 + tid;
  int ixg = tid/36, iyg = (tid/6)%6, izg = tid%6;
  float sx=R7[3], sy=R7[4], sz=R7[5];
  float lx = ((float)ixg + 0.5f)/6.0f * sx - 0.5f*sx;
  float ly = ((float)iyg + 0.5f)/6.0f * sy - 0.5f*sy;
  float lz = ((float)izg + 0.5f)/6.0f * sz - 0.5f*sz;
  float cs = trg[0], sn = trg[1];
  float px = lx*cs - ly*sn + R7[0];
  float py = lx*sn + ly*cs + R7[1];
  float pz = lz + R7[2];
  g_newxyz[3*m]=px; g_newxyz[3*m+1]=py; g_newxyz[3*m+2]=pz;

  const float RS = 0.4001f;
  int ix0 = max((int)floorf((px-RS+50.f)*2.5f), 0);
  int ix1 = min((int)floorf((px+RS+50.f)*2.5f), NXC-1);
  int iy0 = max((int)floorf((py-RS+50.f)*2.5f), 0);
  int iy1 = min((int)floorf((py+RS+50.f)*2.5f), NYC-1);
  int iz0 = max((int)floorf((pz-RS+ 2.f)*2.5f), 0);
  int iz1 = min((int)floorf((pz+RS+ 2.f)*2.5f), NZC-1);

  int lst[16]; int cnt = 0;
  for (int ix=ix0; ix<=ix1; ix++)
    for (int iy=iy0; iy<=iy1; iy++)
      for (int iz=iz0; iz<=iz1; iz++){
        int cell = cellOf(ix,iy,iz);
        int c = g_cellcnt[cell]; c = min(c, CAP);
        for (int t=0; t<c; t++){
          int j = g_celllist[cell*CAP+t];
          float dx = xyz[3*j]-px, dy = xyz[3*j+1]-py, dz = xyz[3*j+2]-pz;
          float d2 = dx*dx + dy*dy + dz*dz;
          if (d2 < 0.16f){
            if (cnt < 16){
              int p = cnt++;
              while (p>0 && lst[p-1]>j){ lst[p]=lst[p-1]; p--; }
              lst[p]=j;
            } else if (j < lst[15]){
              int p = 15;
              while (p>0 && lst[p-1]>j){ lst[p]=lst[p-1]; p--; }
              lst[p]=j;
            }
          }
        }
      }
  g_qcnt[m] = cnt;
  for (int s=0; s<cnt; s++) g_qidx[m*16+s] = lst[s];
}

// ------------------------- fused point-MLP + sparse layer, block per roi -------------------------
__global__ void __launch_bounds__(256) k_cell(
    const float* __restrict__ xyz, const float* __restrict__ feat,
    const float* __restrict__ w0, const float* __restrict__ gg0, const float* __restrict__ bb0,
    const float* __restrict__ w1, const float* __restrict__ gg1, const float* __restrict__ bb1){
  int r = blockIdx.x, tid = threadIdx.x;
  int gq = tid >> 6, lt = tid & 63;     // 4 groups of 64
  __shared__ __align__(16) float sw0s[CMID*CK];      // 2240 f
  __shared__ float sw1s[CMID*65];                    // 4160 f
  __shared__ float sg0[CMID], sb0[CMID], sg1[CMID], sb1[CMID], spe[CMID];
  __shared__ float delta[4][CMID];
  __shared__ __align__(16) float grp[4][16*CK];      // 4*560
  __shared__ float h0s[4][8*CMID];                   // 4*512 (8-sample chunks)
  __shared__ int list[G3], wcnt[8], nn;

  const float4* w04 = (const float4*)w0;
  for (int e=tid; e<560; e+=256) ((float4*)sw0s)[e] = w04[e];
  const float4* w14 = (const float4*)w1;
  for (int e=tid; e<1024; e+=256){
    float4 v = w14[e];
    int c = e>>4, j0 = (e&15)*4;
    float* p = &sw1s[c*65 + j0];
    p[0]=v.x; p[1]=v.y; p[2]=v.z; p[3]=v.w;
  }
  if (tid < 64){
    sg0[tid]=gg0[tid]; sb0[tid]=bb0[tid]; sg1[tid]=gg1[tid]; sb1[tid]=bb1[tid];
    spe[tid]=g_pe[tid];
  }
  // compact nonempty cells of this roi
  int flag = (tid < G3) ? (g_qcnt[r*G3+tid] > 0) : 0;
  unsigned bal = __ballot_sync(0xffffffffu, flag);
  if ((tid&31)==0) wcnt[tid>>5] = __popc(bal);
  __syncthreads();
  if (tid==0){ int s=0; for (int w=0;w<8;w++){ int c=wcnt[w]; wcnt[w]=s; s+=c; } nn=s; }
  __syncthreads();
  if (flag){
    int pos = wcnt[tid>>5] + __popc(bal & ((1u<<(tid&31))-1u));
    list[pos] = tid;
  }
  __syncthreads();

  float acc = g_base[tid];
  int n = nn;
  for (int i=0; i<n; i+=4){
    int myc = i + gq;
    if (myc < n){
      int g = list[myc];
      int m = r*G3 + g;
      int cnt = g_qcnt[m];
      float nx=g_newxyz[3*m], ny=g_newxyz[3*m+1], nz=g_newxyz[3*m+2];
      float* gb = grp[gq];
      for (int e=lt; e<cnt*CK; e+=64){
        int s = e/CK, k = e - s*CK;
        int j = g_qidx[m*16+s];
        float v;
        if (k < 3) v = xyz[3*j+k] - ((k==0)?nx:((k==1)?ny:nz));
        else       v = feat[j*CIN + (k-3)];
        gb[e] = v;
      }
      barg(gq+1);
      float best = 0.f;
      float* hb = h0s[gq];
      for (int s0=0; s0<cnt; s0+=8){
        int ns = min(8, cnt - s0);
        for (int s=0; s<ns; s++){
          float a = 0.f;
          const float* gr = &gb[(s0+s)*CK];
          #pragma unroll
          for (int k=0;k<CK;k++) a += gr[k]*sw0s[lt*CK+k];
          hb[s*CMID+lt] = fmaxf(sg0[lt]*a*BN_INV + sb0[lt], 0.f);
        }
        barg(gq+1);
        for (int s=0; s<ns; s++){
          float a = 0.f;
          const float* hr = &hb[s*CMID];
          #pragma unroll 16
          for (int j=0;j<CMID;j++) a += hr[j]*sw1s[lt*65+j];
          best = fmaxf(best, fmaxf(sg1[lt]*a*BN_INV + sb1[lt], 0.f));
        }
        barg(gq+1);
      }
      delta[gq][lt] = best - spe[lt];
    }
    __syncthreads();
    int nb = min(4, n - i);
    for (int j=0; j<nb; j++){
      int g = list[i+j];
      const float* wp = &g_w0t[(g*CMID)*FCH + tid];
      float a = 0.f;
      #pragma unroll 16
      for (int c=0;c<CMID;c++) a += delta[j][c]*wp[c*FCH];
      acc += a;
    }
    __syncthreads();
  }
  g_x[r*FCH+tid] = fmaxf(acc, 0.f);
}

// ------------------------- fused head MLPs, 4 rois per block -------------------------
__device__ __forceinline__ void layer4(int mat, float X[4][FCH], float Y[4][FCH], int t){
  const float4* P  = (const float4*)&g_wT[mat*FCH*FCH];
  const float4* x0 = (const float4*)X[0];
  const float4* x1 = (const float4*)X[1];
  const float4* x2 = (const float4*)X[2];
  const float4* x3 = (const float4*)X[3];
  float a0=0.f,a1=0.f,a2=0.f,a3=0.f;
  #pragma unroll 8
  for (int k4=0;k4<64;k4++){
    float4 w = P[k4*FCH + t];
    float4 v0=x0[k4], v1=x1[k4], v2=x2[k4], v3=x3[k4];
    a0 += w.x*v0.x + w.y*v0.y + w.z*v0.z + w.w*v0.w;
    a1 += w.x*v1.x + w.y*v1.y + w.z*v1.z + w.w*v1.w;
    a2 += w.x*v2.x + w.y*v2.y + w.z*v2.z + w.w*v2.w;
    a3 += w.x*v3.x + w.y*v3.y + w.z*v3.z + w.w*v3.w;
  }
  Y[0][t]=fmaxf(a0,0.f); Y[1][t]=fmaxf(a1,0.f);
  Y[2][t]=fmaxf(a2,0.f); Y[3][t]=fmaxf(a3,0.f);
  __syncthreads();
}

__global__ void __launch_bounds__(256) k_heads(
    const float* __restrict__ cw2,const float* __restrict__ cb2,
    const float* __restrict__ iw2,const float* __restrict__ ib2,
    const float* __restrict__ rw2,const float* __restrict__ rb2,
    float* __restrict__ out){
  __shared__ __align__(16) float X[4][FCH], Y[4][FCH];
  int t = threadIdx.x;
  int rb = blockIdx.x*4, h = blockIdx.y;
  #pragma unroll
  for (int rr=0; rr<4; rr++) X[rr][t] = g_x[(rb+rr)*FCH + t];
  __syncthreads();
  layer4(0,     X, Y, t);     // shared_w1
  layer4(1+2*h, Y, X, t);     // head layer 0
  layer4(2+2*h, X, Y, t);     // head layer 1
  const float* w2 = (h==0)? cw2 : (h==1)? iw2 : rw2;
  const float* b2 = (h==0)? cb2 : (h==1)? ib2 : rb2;
  int nq  = (h==2)? 7 : 1;
  int off = (h==0)? 0 : (h==1)? RROIS : 2*RROIS;
  int w = t>>5, lane = t&31;
  if (w < 4){
    const float* S = Y[w];
    for (int q=0;q<nq;q++){
      float s = 0.f;
      #pragma unroll
      for (int k=lane;k<FCH;k+=32) s += S[k]*w2[q*FCH+k];
      #pragma unroll
      for (int o2=16;o2;o2>>=1) s += __shfl_down_sync(0xffffffffu, s, o2);
      if (lane==0) out[off + (rb+w)*nq + q] = s + b2[q];
    }
  }
}

// ------------------------- launch -------------------------
extern "C" void kernel_launch(void* const* d_in, const int* in_sizes, int n_in,
                              void* d_out, int out_size){
  const float* xyz    = (const float*)d_in[0];
  const float* feat   = (const float*)d_in[1];
  const float* rois   = (const float*)d_in[2];
  const float* mlp_w0 = (const float*)d_in[3];
  const float* mlp_g0 = (const float*)d_in[4];
  const float* mlp_b0 = (const float*)d_in[5];
  const float* mlp_w1 = (const float*)d_in[6];
  const float* mlp_g1 = (const float*)d_in[7];
  const float* mlp_b1 = (const float*)d_in[8];
  const float* sw0    = (const float*)d_in[9];
  const float* sw1    = (const float*)d_in[10];
  const float* cw0    = (const float*)d_in[11];
  const float* cw1    = (const float*)d_in[12];
  const float* cw2    = (const float*)d_in[13];
  const float* cb2    = (const float*)d_in[14];
  const float* iw0    = (const float*)d_in[15];
  const float* iw1    = (const float*)d_in[16];
  const float* iw2    = (const float*)d_in[17];
  const float* ib2    = (const float*)d_in[18];
  const float* rw0    = (const float*)d_in[19];
  const float* rw1    = (const float*)d_in[20];
  const float* rw2    = (const float*)d_in[21];
  const float* rb2    = (const float*)d_in[22];
  float* out = (float*)d_out;

  k_prep  <<<1403, 256>>>(sw0, sw1, cw0, cw1, iw0, iw1, rw0, rw1,
                          mlp_w1, mlp_g1, mlp_b1, mlp_b0);
  k_insert<<<33, 256>>>(xyz, rois);
  k_query <<<RROIS, 224>>>(xyz, rois);
  k_cell  <<<RROIS, 256>>>(xyz, feat, mlp_w0, mlp_g0, mlp_b0, mlp_w1, mlp_g1, mlp_b1);
  k_heads <<<dim3(RROIS/4, 3), 256>>>(cw2, cb2, iw2, ib2, rw2, rb2, out);
}

// round 5
// speedup vs baseline: 3.7845x; 1.4765x over previous
#include <cuda_runtime.h>
#include <math.h>

#define NPTS   8192
#define RROIS  128
#define G3     216
#define MGRID  (RROIS*G3)
#define NXC    252
#define NYC    252
#define NZC    11
#define NCELL  (NXC*NYC*NZC)      // 698544
#define CAP    8
#define CMID   64
#define CIN    32
#define CK     35
#define FCH    256

// ------------------------- scratch -------------------------
__device__ int   g_cellcnt[NCELL];
__device__ int   g_celllist[NCELL*CAP];
__device__ int   g_nactive;
__device__ int   g_actlist[MGRID];
__device__ int   g_gcnt[G3];
__device__ int   g_glist[G3*RROIS];
__device__ int   g_qcnt[MGRID];
__device__ int   g_qidx[MGRID*16];
__device__ float g_newxyz[MGRID*3];
__device__ float g_trig[2*RROIS];
__device__ float g_delta[MGRID*CMID];
__device__ float g_w0t[G3*CMID*FCH];       // [g*64+c][o], o contiguous
__device__ float g_base[FCH];
__device__ float g_pe[CMID];
__device__ float g_x[RROIS*FCH];
__device__ float g_wT[7*FCH*FCH];          // packed: [mat][k4][o][ki]

#define BN_INV 0.9999949932f

__device__ __forceinline__ int cellOf(int ix,int iy,int iz){ return (ix*NYC+iy)*NZC+iz; }
__device__ __forceinline__ void barg(int id){ asm volatile("bar.sync %0, 64;" :: "r"(id)); }

// ------------------------- fused prep kernel -------------------------
__global__ void k_prep(const float* __restrict__ sw0,
                       const float* __restrict__ m0,const float* __restrict__ m1,
                       const float* __restrict__ m2,const float* __restrict__ m3,
                       const float* __restrict__ m4,const float* __restrict__ m5,
                       const float* __restrict__ m6,
                       const float* __restrict__ w1,const float* __restrict__ g1v,
                       const float* __restrict__ b1v,const float* __restrict__ b0v){
  __shared__ float sh[64*65];
  int b = blockIdx.x, tid = threadIdx.x;
  int tx = tid & 15, ty = tid >> 4;

  if (b < 864){
    int ct = b % 216, ot = b / 216;
    int col0 = ct*64, o0 = ot*64;
    #pragma unroll
    for (int i=0;i<4;i++){
      int r = ty + 16*i;
      float4 v = *(const float4*)&sw0[(size_t)(o0+r)*13824 + col0 + 4*tx];
      float* t = &sh[r*65 + 4*tx];
      t[0]=v.x; t[1]=v.y; t[2]=v.z; t[3]=v.w;
    }
    __syncthreads();
    #pragma unroll
    for (int i=0;i<4;i++){
      int ci = ty + 16*i;
      int col = col0 + ci;
      int c = col / 216, g = col - c*216;
      float4 v;
      v.x = sh[(4*tx+0)*65 + ci];
      v.y = sh[(4*tx+1)*65 + ci];
      v.z = sh[(4*tx+2)*65 + ci];
      v.w = sh[(4*tx+3)*65 + ci];
      *(float4*)&g_w0t[(g*CMID + c)*FCH + o0 + 4*tx] = v;
    }
  } else if (b < 976){
    int bb = b - 864;
    int mat = bb >> 4, tt = bb & 15;
    int kt = tt & 3, ot = tt >> 2;
    const float* W = (mat==0)?m0:(mat==1)?m1:(mat==2)?m2:(mat==3)?m3:(mat==4)?m4:(mat==5)?m5:m6;
    int k0 = kt*64, o0 = ot*64;
    #pragma unroll
    for (int i=0;i<4;i++){
      int r = ty + 16*i;
      float4 v = *(const float4*)&W[(o0+r)*FCH + k0 + 4*tx];
      float* t = &sh[r*65 + 4*tx];
      t[0]=v.x; t[1]=v.y; t[2]=v.z; t[3]=v.w;
    }
    __syncthreads();
    #pragma unroll
    for (int i=0;i<4;i++){
      int idx = tid + 256*i;
      int ol = idx & 63, k4l = idx >> 6;
      float4 v;
      v.x = sh[ol*65 + 4*k4l+0];
      v.y = sh[ol*65 + 4*k4l+1];
      v.z = sh[ol*65 + 4*k4l+2];
      v.w = sh[ol*65 + 4*k4l+3];
      int k4g = (k0>>2) + k4l;
      *(float4*)&g_wT[mat*FCH*FCH + k4g*1024 + (o0+ol)*4] = v;
    }
  } else if (b < 1232){
    int o = b - 976;
    float* spe = sh;
    float* h0e = sh + 64;
    float* red = sh + 128;
    if (tid < 64) h0e[tid] = fmaxf(b0v[tid], 0.f);
    __syncthreads();
    if (tid < 64){
      float acc = 0.f;
      #pragma unroll 8
      for (int j=0;j<CMID;j++) acc += h0e[j]*w1[tid*CMID+j];
      spe[tid] = fmaxf(g1v[tid]*acc*BN_INV + b1v[tid], 0.f);
    }
    __syncthreads();
    float s = 0.f;
    const float4* row4 = (const float4*)&sw0[(size_t)o*13824];
    for (int it=tid; it<3456; it+=256){
      float4 v = row4[it];
      int col = it*4;
      int c0 = col/216; int rem = col - c0*216;
      float p0 = spe[c0];
      float p1 = spe[(rem+1>=216)? c0+1 : c0];
      float p2 = spe[(rem+2>=216)? c0+1 : c0];
      float p3 = spe[(rem+3>=216)? c0+1 : c0];
      s += v.x*p0 + v.y*p1 + v.z*p2 + v.w*p3;
    }
    red[tid] = s; __syncthreads();
    if (tid<128) red[tid] += red[tid+128]; __syncthreads();
    if (tid<64)  red[tid] += red[tid+64];  __syncthreads();
    if (tid<32){
      float v = red[tid] + red[tid+32];
      #pragma unroll
      for (int off=16;off;off>>=1) v += __shfl_down_sync(0xffffffffu, v, off);
      if (tid==0) g_base[o] = v;
    }
    if (b==976 && tid<64) g_pe[tid] = spe[tid];
  } else {
    int d = b - 1232;
    int4 z = make_int4(0,0,0,0);
    for (int i = d*256 + tid; i < NCELL/4; i += 171*256)
      ((int4*)g_cellcnt)[i] = z;
    if (d==0){
      if (tid < G3) g_gcnt[tid] = 0;
      if (tid == 255) g_nactive = 0;
    }
  }
}

// ------------------------- hash insert + per-roi trig -------------------------
__global__ void k_insert(const float* __restrict__ xyz, const float* __restrict__ rois){
  if (blockIdx.x == 32){
    int r = threadIdx.x;
    if (r < RROIS){
      double a = (double)rois[r*7+6];
      g_trig[2*r]   = (float)cos(a);
      g_trig[2*r+1] = (float)sin(a);
    }
    return;
  }
  int i = blockIdx.x*blockDim.x + threadIdx.x;
  float x = xyz[3*i], y = xyz[3*i+1], z = xyz[3*i+2];
  int ix = (int)floorf((x+50.f)*2.5f); ix = min(max(ix,0), NXC-1);
  int iy = (int)floorf((y+50.f)*2.5f); iy = min(max(iy,0), NYC-1);
  int iz = (int)floorf((z+ 2.f)*2.5f); iz = min(max(iz,0), NZC-1);
  int cell = cellOf(ix,iy,iz);
  int slot = atomicAdd(&g_cellcnt[cell], 1);
  if (slot < CAP) g_celllist[cell*CAP+slot] = i;
}

// ------------------------- ball query, block per roi; also inits g_x -------------------------
__global__ void k_query(const float* __restrict__ xyz, const float* __restrict__ rois){
  int r = blockIdx.x, tid = threadIdx.x;
  __shared__ float R7[7], trg[2];
  if (tid < 7) R7[tid] = rois[r*7+tid];
  if (tid < 2) trg[tid] = g_trig[2*r+tid];
  __syncthreads();
  g_x[r*FCH + tid] = g_base[tid];           // init sparse-layer accumulator
  if (tid >= G3) return;
  int m = r*G3 + tid;
  int ixg = tid/36, iyg = (tid/6)%6, izg = tid%6;
  float sx=R7[3], sy=R7[4], sz=R7[5];
  float lx = ((float)ixg + 0.5f)/6.0f * sx - 0.5f*sx;
  float ly = ((float)iyg + 0.5f)/6.0f * sy - 0.5f*sy;
  float lz = ((float)izg + 0.5f)/6.0f * sz - 0.5f*sz;
  float cs = trg[0], sn = trg[1];
  float px = lx*cs - ly*sn + R7[0];
  float py = lx*sn + ly*cs + R7[1];
  float pz = lz + R7[2];
  g_newxyz[3*m]=px; g_newxyz[3*m+1]=py; g_newxyz[3*m+2]=pz;

  const float RS = 0.4001f;
  int ix0 = max((int)floorf((px-RS+50.f)*2.5f), 0);
  int ix1 = min((int)floorf((px+RS+50.f)*2.5f), NXC-1);
  int iy0 = max((int)floorf((py-RS+50.f)*2.5f), 0);
  int iy1 = min((int)floorf((py+RS+50.f)*2.5f), NYC-1);
  int iz0 = max((int)floorf((pz-RS+ 2.f)*2.5f), 0);
  int iz1 = min((int)floorf((pz+RS+ 2.f)*2.5f), NZC-1);

  int lst[16]; int cnt = 0;
  for (int ix=ix0; ix<=ix1; ix++)
    for (int iy=iy0; iy<=iy1; iy++)
      for (int iz=iz0; iz<=iz1; iz++){
        int cell = cellOf(ix,iy,iz);
        int c = g_cellcnt[cell]; c = min(c, CAP);
        for (int t=0; t<c; t++){
          int j = g_celllist[cell*CAP+t];
          float dx = xyz[3*j]-px, dy = xyz[3*j+1]-py, dz = xyz[3*j+2]-pz;
          float d2 = dx*dx + dy*dy + dz*dz;
          if (d2 < 0.16f){
            if (cnt < 16){
              int p = cnt++;
              while (p>0 && lst[p-1]>j){ lst[p]=lst[p-1]; p--; }
              lst[p]=j;
            } else if (j < lst[15]){
              int p = 15;
              while (p>0 && lst[p-1]>j){ lst[p]=lst[p-1]; p--; }
              lst[p]=j;
            }
          }
        }
      }
  g_qcnt[m] = cnt;
  for (int s=0; s<cnt; s++) g_qidx[m*16+s] = lst[s];
  if (cnt > 0){
    int p = atomicAdd(&g_nactive, 1); g_actlist[p] = m;
    int s = atomicAdd(&g_gcnt[tid], 1); g_glist[tid*RROIS+s] = r;
  }
}

// ------------------------- point MLP: delta per active cell -------------------------
__global__ void __launch_bounds__(256) k_mlp(
    const float* __restrict__ xyz, const float* __restrict__ feat,
    const float* __restrict__ w0, const float* __restrict__ gg0, const float* __restrict__ bb0,
    const float* __restrict__ w1, const float* __restrict__ gg1, const float* __restrict__ bb1){
  int tid = threadIdx.x;
  int gq = tid >> 6, lt = tid & 63;     // 4 groups of 64
  __shared__ __align__(16) float sw0s[CMID*CK];
  __shared__ float sw1s[CMID*65];
  __shared__ float sg0[CMID], sb0[CMID], sg1[CMID], sb1[CMID], spe[CMID];
  __shared__ __align__(16) float grp[4][16*CK];
  __shared__ float h0s[4][8*CMID];

  const float4* w04 = (const float4*)w0;
  for (int e=tid; e<560; e+=256) ((float4*)sw0s)[e] = w04[e];
  const float4* w14 = (const float4*)w1;
  for (int e=tid; e<1024; e+=256){
    float4 v = w14[e];
    int c = e>>4, j0 = (e&15)*4;
    float* p = &sw1s[c*65 + j0];
    p[0]=v.x; p[1]=v.y; p[2]=v.z; p[3]=v.w;
  }
  if (tid < 64){
    sg0[tid]=gg0[tid]; sb0[tid]=bb0[tid]; sg1[tid]=gg1[tid]; sb1[tid]=bb1[tid];
    spe[tid]=g_pe[tid];
  }
  __syncthreads();
  int nact = g_nactive;

  for (int i = blockIdx.x*4 + gq; i < nact; i += gridDim.x*4){
    int m   = g_actlist[i];
    int cnt = g_qcnt[m];
    float nx=g_newxyz[3*m], ny=g_newxyz[3*m+1], nz=g_newxyz[3*m+2];
    float* gb = grp[gq];
    for (int e=lt; e<cnt*CK; e+=64){
      int s = e/CK, k = e - s*CK;
      int j = g_qidx[m*16+s];
      float v;
      if (k < 3) v = xyz[3*j+k] - ((k==0)?nx:((k==1)?ny:nz));
      else       v = feat[j*CIN + (k-3)];
      gb[e] = v;
    }
    barg(gq+1);
    float best = 0.f;
    float* hb = h0s[gq];
    for (int s0=0; s0<cnt; s0+=8){
      int ns = min(8, cnt - s0);
      for (int s=0; s<ns; s++){
        float a = 0.f;
        const float* gr = &gb[(s0+s)*CK];
        #pragma unroll
        for (int k=0;k<CK;k++) a += gr[k]*sw0s[lt*CK+k];
        hb[s*CMID+lt] = fmaxf(sg0[lt]*a*BN_INV + sb0[lt], 0.f);
      }
      barg(gq+1);
      for (int s=0; s<ns; s++){
        float a = 0.f;
        const float* hr = &hb[s*CMID];
        #pragma unroll 16
        for (int j=0;j<CMID;j++) a += hr[j]*sw1s[lt*65+j];
        best = fmaxf(best, fmaxf(sg1[lt]*a*BN_INV + sb1[lt], 0.f));
      }
      barg(gq+1);
    }
    g_delta[m*CMID + lt] = best - spe[lt];
  }
}

// ------------------------- sparse scatter: one block per (grid-cell, o-half) -------------------------
__global__ void __launch_bounds__(128) k_sh0g(){
  int b = blockIdx.x;
  int g = b >> 1, half = b & 1;
  int tid = threadIdx.x;
  int ng = g_gcnt[g];
  if (ng == 0) return;
  __shared__ __align__(16) float sw[CMID*128];   // 32KB: w0t[g][c][half*128 + o]
  __shared__ float sdelta[CMID];
  const float4* s4 = (const float4*)g_w0t;
  float4* sw4 = (float4*)sw;
  for (int i=tid; i<2048; i+=128){
    int c = i >> 5, o4 = i & 31;
    sw4[c*32 + o4] = s4[(size_t)(g*CMID + c)*64 + half*32 + o4];
  }
  __syncthreads();
  int o = half*128 + tid;
  for (int t=0; t<ng; t++){
    int r = g_glist[g*RROIS + t];
    int m = r*G3 + g;
    if (tid < CMID) sdelta[tid] = g_delta[m*CMID + tid];
    __syncthreads();
    float acc = 0.f;
    #pragma unroll 16
    for (int c=0;c<CMID;c++) acc += sdelta[c]*sw[c*128 + tid];
    atomicAdd(&g_x[r*FCH + o], acc);
    __syncthreads();
  }
}

// ------------------------- fused head MLPs, 4 rois per block -------------------------
__device__ __forceinline__ void layer4(int mat, float X[4][FCH], float Y[4][FCH], int t){
  const float4* P  = (const float4*)&g_wT[mat*FCH*FCH];
  const float4* x0 = (const float4*)X[0];
  const float4* x1 = (const float4*)X[1];
  const float4* x2 = (const float4*)X[2];
  const float4* x3 = (const float4*)X[3];
  float a0=0.f,a1=0.f,a2=0.f,a3=0.f;
  #pragma unroll 8
  for (int k4=0;k4<64;k4++){
    float4 w = P[k4*FCH + t];
    float4 v0=x0[k4], v1=x1[k4], v2=x2[k4], v3=x3[k4];
    a0 += w.x*v0.x + w.y*v0.y + w.z*v0.z + w.w*v0.w;
    a1 += w.x*v1.x + w.y*v1.y + w.z*v1.z + w.w*v1.w;
    a2 += w.x*v2.x + w.y*v2.y + w.z*v2.z + w.w*v2.w;
    a3 += w.x*v3.x + w.y*v3.y + w.z*v3.z + w.w*v3.w;
  }
  Y[0][t]=fmaxf(a0,0.f); Y[1][t]=fmaxf(a1,0.f);
  Y[2][t]=fmaxf(a2,0.f); Y[3][t]=fmaxf(a3,0.f);
  __syncthreads();
}

__global__ void __launch_bounds__(256) k_heads(
    const float* __restrict__ cw2,const float* __restrict__ cb2,
    const float* __restrict__ iw2,const float* __restrict__ ib2,
    const float* __restrict__ rw2,const float* __restrict__ rb2,
    float* __restrict__ out){
  __shared__ __align__(16) float X[4][FCH], Y[4][FCH];
  int t = threadIdx.x;
  int rb = blockIdx.x*4, h = blockIdx.y;
  #pragma unroll
  for (int rr=0; rr<4; rr++) X[rr][t] = fmaxf(g_x[(rb+rr)*FCH + t], 0.f);
  __syncthreads();
  layer4(0,     X, Y, t);     // shared_w1
  layer4(1+2*h, Y, X, t);     // head layer 0
  layer4(2+2*h, X, Y, t);     // head layer 1
  const float* w2 = (h==0)? cw2 : (h==1)? iw2 : rw2;
  const float* b2 = (h==0)? cb2 : (h==1)? ib2 : rb2;
  int nq  = (h==2)? 7 : 1;
  int off = (h==0)? 0 : (h==1)? RROIS : 2*RROIS;
  int w = t>>5, lane = t&31;
  if (w < 4){
    const float* S = Y[w];
    for (int q=0;q<nq;q++){
      float s = 0.f;
      #pragma unroll
      for (int k=lane;k<FCH;k+=32) s += S[k]*w2[q*FCH+k];
      #pragma unroll
      for (int o2=16;o2;o2>>=1) s += __shfl_down_sync(0xffffffffu, s, o2);
      if (lane==0) out[off + (rb+w)*nq + q] = s + b2[q];
    }
  }
}

// ------------------------- launch -------------------------
extern "C" void kernel_launch(void* const* d_in, const int* in_sizes, int n_in,
                              void* d_out, int out_size){
  const float* xyz    = (const float*)d_in[0];
  const float* feat   = (const float*)d_in[1];
  const float* rois   = (const float*)d_in[2];
  const float* mlp_w0 = (const float*)d_in[3];
  const float* mlp_g0 = (const float*)d_in[4];
  const float* mlp_b0 = (const float*)d_in[5];
  const float* mlp_w1 = (const float*)d_in[6];
  const float* mlp_g1 = (const float*)d_in[7];
  const float* mlp_b1 = (const float*)d_in[8];
  const float* sw0    = (const float*)d_in[9];
  const float* sw1    = (const float*)d_in[10];
  const float* cw0    = (const float*)d_in[11];
  const float* cw1    = (const float*)d_in[12];
  const float* cw2    = (const float*)d_in[13];
  const float* cb2    = (const float*)d_in[14];
  const float* iw0    = (const float*)d_in[15];
  const float* iw1    = (const float*)d_in[16];
  const float* iw2    = (const float*)d_in[17];
  const float* ib2    = (const float*)d_in[18];
  const float* rw0    = (const float*)d_in[19];
  const float* rw1    = (const float*)d_in[20];
  const float* rw2    = (const float*)d_in[21];
  const float* rb2    = (const float*)d_in[22];
  float* out = (float*)d_out;

  k_prep  <<<1403, 256>>>(sw0, sw1, cw0, cw1, iw0, iw1, rw0, rw1,
                          mlp_w1, mlp_g1, mlp_b1, mlp_b0);
  k_insert<<<33, 256>>>(xyz, rois);
  k_query <<<RROIS, 256>>>(xyz, rois);
  k_mlp   <<<352, 256>>>(xyz, feat, mlp_w0, mlp_g0, mlp_b0, mlp_w1, mlp_g1, mlp_b1);
  k_sh0g  <<<2*G3, 128>>>();
  k_heads <<<dim3(RROIS/4, 3), 256>>>(cw2, cb2, iw2, ib2, rw2, rb2, out);
}

// round 7
// speedup vs baseline: 4.0156x; 1.0611x over previous
#include <cuda_runtime.h>
#include <math.h>

#define NPTS   8192
#define RROIS  128
#define G3     216
#define MGRID  (RROIS*G3)
#define NXC    252
#define NYC    252
#define NZC    11
#define NCELL  (NXC*NYC*NZC)      // 698544
#define CAP    8
#define CMID   64
#define CIN    32
#define CK     35
#define FCH    256

// ------------------------- scratch -------------------------
__device__ int    g_cellcnt[NCELL];
__device__ float4 g_cellpts[NCELL*CAP];    // (x,y,z, bitcast(index))
__device__ int    g_nactive;
__device__ int    g_actlist[MGRID];
__device__ int    g_gcnt[G3];
__device__ int    g_glist[G3*RROIS];
__device__ int    g_qcnt[MGRID];
__device__ int    g_qidx[MGRID*16];
__device__ float  g_newxyz[MGRID*3];
__device__ float  g_trig[2*RROIS];
__device__ float  g_delta[MGRID*CMID];
__device__ float  g_w0t[G3*CMID*FCH];      // [g*64+c][o], o contiguous
__device__ float  g_base[FCH];
__device__ float  g_x[RROIS*FCH];          // zeroed in prep; atomically accumulated
__device__ float  g_wT[7*FCH*FCH];         // packed: [mat][k4][o][ki]

#define BN_INV 0.9999949932f

__device__ __forceinline__ int cellOf(int ix,int iy,int iz){ return (ix*NYC+iy)*NZC+iz; }
__device__ __forceinline__ void barg(int id){ asm volatile("bar.sync %0, 64;" :: "r"(id)); }

// ------------------------- fused prep kernel (runs on side stream) -------------------------
__global__ void k_prep(const float* __restrict__ sw0,
                       const float* __restrict__ m0,const float* __restrict__ m1,
                       const float* __restrict__ m2,const float* __restrict__ m3,
                       const float* __restrict__ m4,const float* __restrict__ m5,
                       const float* __restrict__ m6,
                       const float* __restrict__ w1,const float* __restrict__ g1v,
                       const float* __restrict__ b1v,const float* __restrict__ b0v){
  __shared__ float sh[64*65];
  int b = blockIdx.x, tid = threadIdx.x;
  int tx = tid & 15, ty = tid >> 4;

  if (b < 864){
    int ct = b % 216, ot = b / 216;
    int col0 = ct*64, o0 = ot*64;
    #pragma unroll
    for (int i=0;i<4;i++){
      int r = ty + 16*i;
      float4 v = *(const float4*)&sw0[(size_t)(o0+r)*13824 + col0 + 4*tx];
      float* t = &sh[r*65 + 4*tx];
      t[0]=v.x; t[1]=v.y; t[2]=v.z; t[3]=v.w;
    }
    __syncthreads();
    #pragma unroll
    for (int i=0;i<4;i++){
      int ci = ty + 16*i;
      int col = col0 + ci;
      int c = col / 216, g = col - c*216;
      float4 v;
      v.x = sh[(4*tx+0)*65 + ci];
      v.y = sh[(4*tx+1)*65 + ci];
      v.z = sh[(4*tx+2)*65 + ci];
      v.w = sh[(4*tx+3)*65 + ci];
      *(float4*)&g_w0t[(g*CMID + c)*FCH + o0 + 4*tx] = v;
    }
  } else if (b < 976){
    int bb = b - 864;
    int mat = bb >> 4, tt = bb & 15;
    int kt = tt & 3, ot = tt >> 2;
    const float* W = (mat==0)?m0:(mat==1)?m1:(mat==2)?m2:(mat==3)?m3:(mat==4)?m4:(mat==5)?m5:m6;
    int k0 = kt*64, o0 = ot*64;
    #pragma unroll
    for (int i=0;i<4;i++){
      int r = ty + 16*i;
      float4 v = *(const float4*)&W[(o0+r)*FCH + k0 + 4*tx];
      float* t = &sh[r*65 + 4*tx];
      t[0]=v.x; t[1]=v.y; t[2]=v.z; t[3]=v.w;
    }
    __syncthreads();
    #pragma unroll
    for (int i=0;i<4;i++){
      int idx = tid + 256*i;
      int ol = idx & 63, k4l = idx >> 6;
      float4 v;
      v.x = sh[ol*65 + 4*k4l+0];
      v.y = sh[ol*65 + 4*k4l+1];
      v.z = sh[ol*65 + 4*k4l+2];
      v.w = sh[ol*65 + 4*k4l+3];
      int k4g = (k0>>2) + k4l;
      *(float4*)&g_wT[mat*FCH*FCH + k4g*1024 + (o0+ol)*4] = v;
    }
  } else if (b < 1232){
    int o = b - 976;
    float* spe = sh;
    float* h0e = sh + 64;
    float* red = sh + 128;
    if (tid < 64) h0e[tid] = fmaxf(b0v[tid], 0.f);
    __syncthreads();
    if (tid < 64){
      float acc = 0.f;
      #pragma unroll 8
      for (int j=0;j<CMID;j++) acc += h0e[j]*w1[tid*CMID+j];
      spe[tid] = fmaxf(g1v[tid]*acc*BN_INV + b1v[tid], 0.f);
    }
    __syncthreads();
    float s = 0.f;
    const float4* row4 = (const float4*)&sw0[(size_t)o*13824];
    for (int it=tid; it<3456; it+=256){
      float4 v = row4[it];
      int col = it*4;
      int c0 = col/216; int rem = col - c0*216;
      float p0 = spe[c0];
      float p1 = spe[(rem+1>=216)? c0+1 : c0];
      float p2 = spe[(rem+2>=216)? c0+1 : c0];
      float p3 = spe[(rem+3>=216)? c0+1 : c0];
      s += v.x*p0 + v.y*p1 + v.z*p2 + v.w*p3;
    }
    red[tid] = s; __syncthreads();
    if (tid<128) red[tid] += red[tid+128]; __syncthreads();
    if (tid<64)  red[tid] += red[tid+64];  __syncthreads();
    if (tid<32){
      float v = red[tid] + red[tid+32];
      #pragma unroll
      for (int off=16;off;off>>=1) v += __shfl_down_sync(0xffffffffu, v, off);
      if (tid==0) g_base[o] = v;
    }
  } else {
    // zero g_x (8192 float4)
    int d = b - 1232;            // 32 blocks
    int4 z = make_int4(0,0,0,0);
    for (int i = d*256 + tid; i < RROIS*FCH/4; i += 32*256)
      ((int4*)g_x)[i] = z;
  }
}

// ------------------------- zero cell counters (main stream, before insert) -------------------------
__global__ void k_zero(){
  int4 z = make_int4(0,0,0,0);
  int i = blockIdx.x*256 + threadIdx.x;
  if (i < NCELL/4) ((int4*)g_cellcnt)[i] = z;
}

// ------------------------- hash insert + per-roi trig + small zeroing -------------------------
__global__ void k_insert(const float* __restrict__ xyz, const float* __restrict__ rois){
  int tid = threadIdx.x;
  if (blockIdx.x == 32){
    if (tid < RROIS){
      double a = (double)rois[tid*7+6];
      g_trig[2*tid]   = (float)cos(a);
      g_trig[2*tid+1] = (float)sin(a);
    }
    if (tid < G3) g_gcnt[tid] = 0;
    if (tid == 255) g_nactive = 0;
    return;
  }
  int i = blockIdx.x*blockDim.x + tid;
  float x = xyz[3*i], y = xyz[3*i+1], z = xyz[3*i+2];
  int ix = (int)floorf((x+50.f)*2.5f); ix = min(max(ix,0), NXC-1);
  int iy = (int)floorf((y+50.f)*2.5f); iy = min(max(iy,0), NYC-1);
  int iz = (int)floorf((z+ 2.f)*2.5f); iz = min(max(iz,0), NZC-1);
  int cell = cellOf(ix,iy,iz);
  int slot = atomicAdd(&g_cellcnt[cell], 1);
  if (slot < CAP){
    float4 p; p.x=x; p.y=y; p.z=z; p.w=__int_as_float(i);
    g_cellpts[cell*CAP+slot] = p;
  }
}

// ------------------------- ball query, block per roi -------------------------
__global__ void k_query(const float* __restrict__ xyz, const float* __restrict__ rois){
  int r = blockIdx.x, tid = threadIdx.x;
  __shared__ float R7[7], trg[2];
  if (tid < 7) R7[tid] = rois[r*7+tid];
  if (tid < 2) trg[tid] = g_trig[2*r+tid];
  __syncthreads();
  if (tid >= G3) return;
  int m = r*G3 + tid;
  int ixg = tid/36, iyg = (tid/6)%6, izg = tid%6;
  float sx=R7[3], sy=R7[4], sz=R7[5];
  float lx = ((float)ixg + 0.5f)/6.0f * sx - 0.5f*sx;
  float ly = ((float)iyg + 0.5f)/6.0f * sy - 0.5f*sy;
  float lz = ((float)izg + 0.5f)/6.0f * sz - 0.5f*sz;
  float cs = trg[0], sn = trg[1];
  float px = lx*cs - ly*sn + R7[0];
  float py = lx*sn + ly*cs + R7[1];
  float pz = lz + R7[2];
  g_newxyz[3*m]=px; g_newxyz[3*m+1]=py; g_newxyz[3*m+2]=pz;

  const float RS = 0.4001f;
  int ix0 = max((int)floorf((px-RS+50.f)*2.5f), 0);
  int ix1 = min((int)floorf((px+RS+50.f)*2.5f), NXC-1);
  int iy0 = max((int)floorf((py-RS+50.f)*2.5f), 0);
  int iy1 = min((int)floorf((py+RS+50.f)*2.5f), NYC-1);
  int iz0 = max((int)floorf((pz-RS+ 2.f)*2.5f), 0);
  int iz1 = min((int)floorf((pz+RS+ 2.f)*2.5f), NZC-1);

  int lst[16]; int cnt = 0;
  for (int ix=ix0; ix<=ix1; ix++)
    for (int iy=iy0; iy<=iy1; iy++)
      for (int iz=iz0; iz<=iz1; iz++){
        int cell = cellOf(ix,iy,iz);
        int c = g_cellcnt[cell]; c = min(c, CAP);
        const float4* cp = &g_cellpts[cell*CAP];
        for (int t=0; t<c; t++){
          float4 p = cp[t];
          float dx = p.x-px, dy = p.y-py, dz = p.z-pz;
          float d2 = dx*dx + dy*dy + dz*dz;
          if (d2 < 0.16f){
            int j = __float_as_int(p.w);
            if (cnt < 16){
              int q = cnt++;
              while (q>0 && lst[q-1]>j){ lst[q]=lst[q-1]; q--; }
              lst[q]=j;
            } else if (j < lst[15]){
              int q = 15;
              while (q>0 && lst[q-1]>j){ lst[q]=lst[q-1]; q--; }
              lst[q]=j;
            }
          }
        }
      }
  g_qcnt[m] = cnt;
  for (int s=0; s<cnt; s++) g_qidx[m*16+s] = lst[s];
  if (cnt > 0){
    int p = atomicAdd(&g_nactive, 1); g_actlist[p] = m;
    int s = atomicAdd(&g_gcnt[tid], 1); g_glist[tid*RROIS+s] = r;
  }
}

// ------------------------- point MLP: delta per active cell -------------------------
__global__ void __launch_bounds__(256) k_mlp(
    const float* __restrict__ xyz, const float* __restrict__ feat,
    const float* __restrict__ w0, const float* __restrict__ gg0, const float* __restrict__ bb0,
    const float* __restrict__ w1, const float* __restrict__ gg1, const float* __restrict__ bb1){
  int tid = threadIdx.x;
  int gq = tid >> 6, lt = tid & 63;     // 4 groups of 64
  __shared__ __align__(16) float sw0s[CMID*CK];
  __shared__ float sw1s[CMID*65];
  __shared__ float sg0[CMID], sb0[CMID], sg1[CMID], sb1[CMID], spe[CMID];
  __shared__ __align__(16) float grp[4][16*CK];
  __shared__ float h0s[4][8*CMID];

  const float4* w04 = (const float4*)w0;
  for (int e=tid; e<560; e+=256) ((float4*)sw0s)[e] = w04[e];
  const float4* w14 = (const float4*)w1;
  for (int e=tid; e<1024; e+=256){
    float4 v = w14[e];
    int c = e>>4, j0 = (e&15)*4;
    float* p = &sw1s[c*65 + j0];
    p[0]=v.x; p[1]=v.y; p[2]=v.z; p[3]=v.w;
  }
  if (tid < 64){
    sg0[tid]=gg0[tid]; sb0[tid]=bb0[tid]; sg1[tid]=gg1[tid]; sb1[tid]=bb1[tid];
  }
  __syncthreads();
  // empty-cell pooled vector computed locally (prep-independent)
  if (tid < 64){
    float a = 0.f;
    #pragma unroll 16
    for (int j=0;j<CMID;j++) a += fmaxf(sb0[j],0.f)*sw1s[tid*65+j];
    spe[tid] = fmaxf(sg1[tid]*a*BN_INV + sb1[tid], 0.f);
  }
  __syncthreads();
  int nact = g_nactive;

  for (int i = blockIdx.x*4 + gq; i < nact; i += gridDim.x*4){
    int m   = g_actlist[i];
    int cnt = g_qcnt[m];
    float nx=g_newxyz[3*m], ny=g_newxyz[3*m+1], nz=g_newxyz[3*m+2];
    float* gb = grp[gq];
    for (int e=lt; e<cnt*CK; e+=64){
      int s = e/CK, k = e - s*CK;
      int j = g_qidx[m*16+s];
      float v;
      if (k < 3) v = xyz[3*j+k] - ((k==0)?nx:((k==1)?ny:nz));
      else       v = feat[j*CIN + (k-3)];
      gb[e] = v;
    }
    barg(gq+1);
    float best = 0.f;
    float* hb = h0s[gq];
    for (int s0=0; s0<cnt; s0+=8){
      int ns = min(8, cnt - s0);
      for (int s=0; s<ns; s++){
        float a = 0.f;
        const float* gr = &gb[(s0+s)*CK];
        #pragma unroll
        for (int k=0;k<CK;k++) a += gr[k]*sw0s[lt*CK+k];
        hb[s*CMID+lt] = fmaxf(sg0[lt]*a*BN_INV + sb0[lt], 0.f);
      }
      barg(gq+1);
      for (int s=0; s<ns; s++){
        float a = 0.f;
        const float* hr = &hb[s*CMID];
        #pragma unroll 16
        for (int j=0;j<CMID;j++) a += hr[j]*sw1s[lt*65+j];
        best = fmaxf(best, fmaxf(sg1[lt]*a*BN_INV + sb1[lt], 0.f));
      }
      barg(gq+1);
    }
    g_delta[m*CMID + lt] = best - spe[lt];
  }
}

// ------------------------- sparse scatter: one block per (grid-cell, o-half) -------------------------
__global__ void __launch_bounds__(128) k_sh0g(){
  int b = blockIdx.x;
  int g = b >> 1, half = b & 1;
  int tid = threadIdx.x;
  int ng = g_gcnt[g];
  if (ng == 0) return;
  __shared__ __align__(16) float sw[CMID*128];   // 32KB
  __shared__ float sdelta[CMID];
  const float4* s4 = (const float4*)g_w0t;
  float4* sw4 = (float4*)sw;
  for (int i=tid; i<2048; i+=128){
    int c = i >> 5, o4 = i & 31;
    sw4[c*32 + o4] = s4[(size_t)(g*CMID + c)*64 + half*32 + o4];
  }
  __syncthreads();
  int o = half*128 + tid;
  for (int t=0; t<ng; t++){
    int r = g_glist[g*RROIS + t];
    int m = r*G3 + g;
    if (tid < CMID) sdelta[tid] = g_delta[m*CMID + tid];
    __syncthreads();
    float acc = 0.f;
    #pragma unroll 16
    for (int c=0;c<CMID;c++) acc += sdelta[c]*sw[c*128 + tid];
    atomicAdd(&g_x[r*FCH + o], acc);
    __syncthreads();
  }
}

// ------------------------- fused head MLPs, 4 rois per block -------------------------
__device__ __forceinline__ void layer4(int mat, float X[4][FCH], float Y[4][FCH], int t){
  const float4* P  = (const float4*)&g_wT[mat*FCH*FCH];
  const float4* x0 = (const float4*)X[0];
  const float4* x1 = (const float4*)X[1];
  const float4* x2 = (const float4*)X[2];
  const float4* x3 = (const float4*)X[3];
  float a0=0.f,a1=0.f,a2=0.f,a3=0.f;
  #pragma unroll 8
  for (int k4=0;k4<64;k4++){
    float4 w = P[k4*FCH + t];
    float4 v0=x0[k4], v1=x1[k4], v2=x2[k4], v3=x3[k4];
    a0 += w.x*v0.x + w.y*v0.y + w.z*v0.z + w.w*v0.w;
    a1 += w.x*v1.x + w.y*v1.y + w.z*v1.z + w.w*v1.w;
    a2 += w.x*v2.x + w.y*v2.y + w.z*v2.z + w.w*v2.w;
    a3 += w.x*v3.x + w.y*v3.y + w.z*v3.z + w.w*v3.w;
  }
  Y[0][t]=fmaxf(a0,0.f); Y[1][t]=fmaxf(a1,0.f);
  Y[2][t]=fmaxf(a2,0.f); Y[3][t]=fmaxf(a3,0.f);
  __syncthreads();
}

__global__ void __launch_bounds__(256) k_heads(
    const float* __restrict__ cw2,const float* __restrict__ cb2,
    const float* __restrict__ iw2,const float* __restrict__ ib2,
    const float* __restrict__ rw2,const float* __restrict__ rb2,
    float* __restrict__ out){
  __shared__ __align__(16) float X[4][FCH], Y[4][FCH];
  int t = threadIdx.x;
  int rb = blockIdx.x*4, h = blockIdx.y;
  float base = g_base[t];
  #pragma unroll
  for (int rr=0; rr<4; rr++) X[rr][t] = fmaxf(g_x[(rb+rr)*FCH + t] + base, 0.f);
  __syncthreads();
  layer4(0,     X, Y, t);     // shared_w1
  layer4(1+2*h, Y, X, t);     // head layer 0
  layer4(2+2*h, X, Y, t);     // head layer 1
  const float* w2 = (h==0)? cw2 : (h==1)? iw2 : rw2;
  const float* b2 = (h==0)? cb2 : (h==1)? ib2 : rb2;
  int nq  = (h==2)? 7 : 1;
  int off = (h==0)? 0 : (h==1)? RROIS : 2*RROIS;
  int w = t>>5, lane = t&31;
  if (w < 4){
    const float* S = Y[w];
    for (int q=0;q<nq;q++){
      float s = 0.f;
      #pragma unroll
      for (int k=lane;k<FCH;k+=32) s += S[k]*w2[q*FCH+k];
      #pragma unroll
      for (int o2=16;o2;o2>>=1) s += __shfl_down_sync(0xffffffffu, s, o2);
      if (lane==0) out[off + (rb+w)*nq + q] = s + b2[q];
    }
  }
}

// ------------------------- launch -------------------------
extern "C" void kernel_launch(void* const* d_in, const int* in_sizes, int n_in,
                              void* d_out, int out_size){
  const float* xyz    = (const float*)d_in[0];
  const float* feat   = (const float*)d_in[1];
  const float* rois   = (const float*)d_in[2];
  const float* mlp_w0 = (const float*)d_in[3];
  const float* mlp_g0 = (const float*)d_in[4];
  const float* mlp_b0 = (const float*)d_in[5];
  const float* mlp_w1 = (const float*)d_in[6];
  const float* mlp_g1 = (const float*)d_in[7];
  const float* mlp_b1 = (const float*)d_in[8];
  const float* sw0    = (const float*)d_in[9];
  const float* sw1    = (const float*)d_in[10];
  const float* cw0    = (const float*)d_in[11];
  const float* cw1    = (const float*)d_in[12];
  const float* cw2    = (const float*)d_in[13];
  const float* cb2    = (const float*)d_in[14];
  const float* iw0    = (const float*)d_in[15];
  const float* iw1    = (const float*)d_in[16];
  const float* iw2    = (const float*)d_in[17];
  const float* ib2    = (const float*)d_in[18];
  const float* rw0    = (const float*)d_in[19];
  const float* rw1    = (const float*)d_in[20];
  const float* rw2    = (const float*)d_in[21];
  const float* rb2    = (const float*)d_in[22];
  float* out = (float*)d_out;

  // side stream for weight prep (fork/join via events; graph-capture safe)
  cudaStream_t s2;
  cudaStreamCreateWithFlags(&s2, cudaStreamNonBlocking);
  cudaEvent_t eF, eJ;
  cudaEventCreateWithFlags(&eF, cudaEventDisableTiming);
  cudaEventCreateWithFlags(&eJ, cudaEventDisableTiming);

  cudaEventRecord(eF, 0);
  cudaStreamWaitEvent(s2, eF, 0);
  k_prep<<<1264, 256, 0, s2>>>(sw0, sw1, cw0, cw1, iw0, iw1, rw0, rw1,
                               mlp_w1, mlp_g1, mlp_b1, mlp_b0);
  cudaEventRecord(eJ, s2);

  // main (legacy) stream: geometry chain
  k_zero  <<<(NCELL/4+255)/256, 256>>>();
  k_insert<<<33, 256>>>(xyz, rois);
  k_query <<<RROIS, 256>>>(xyz, rois);
  k_mlp   <<<352, 256>>>(xyz, feat, mlp_w0, mlp_g0, mlp_b0, mlp_w1, mlp_g1, mlp_b1);

  cudaStreamWaitEvent(0, eJ, 0);   // join: sh0g needs w0t, heads needs wT/base
  k_sh0g  <<<2*G3, 128>>>();
  k_heads <<<dim3(RROIS/4, 3), 256>>>(cw2, cb2, iw2, ib2, rw2, rb2, out);
}